// round 1
// baseline (speedup 1.0000x reference)
#include <cuda_runtime.h>
#include <math.h>

#define N_NODES 100000
#define N_EDGES 1280000
#define DIM 64

// Scratch (allocation-free rule: __device__ globals)
__device__ float g_agg[(size_t)N_NODES * DIM];   // 25.6 MB
__device__ float g_deg[N_NODES];

// ---------------------------------------------------------------------------
// Kernel 1: zero the scratch accumulators (vectorized)
// ---------------------------------------------------------------------------
__global__ __launch_bounds__(256) void zero_kernel() {
    size_t i = (size_t)blockIdx.x * blockDim.x + threadIdx.x;
    const size_t n4 = (size_t)N_NODES * DIM / 4;   // 1.6M float4
    float4 z = make_float4(0.f, 0.f, 0.f, 0.f);
    if (i < n4) ((float4*)g_agg)[i] = z;
    if (i < N_NODES) g_deg[i] = 0.f;
}

// ---------------------------------------------------------------------------
// Kernel 2: edge scatter.  16 threads per edge; each thread moves one float4.
// Gather features[src] (L2-resident), scale by w, vector-RED into g_agg[dst].
// ---------------------------------------------------------------------------
__global__ __launch_bounds__(256) void edge_kernel(
    const float* __restrict__ feat,
    const float* __restrict__ w,
    const int*   __restrict__ src,
    const int*   __restrict__ dst)
{
    unsigned t    = blockIdx.x * blockDim.x + threadIdx.x;
    unsigned e    = t >> 4;
    unsigned lane = t & 15;
    if (e >= N_EDGES) return;

    int   s  = __ldg(src + e);
    int   d  = __ldg(dst + e);
    float we = __ldg(w + e);

    float4 f = __ldg((const float4*)(feat + (size_t)s * DIM) + lane);
    f.x *= we; f.y *= we; f.z *= we; f.w *= we;

    float* p = g_agg + (size_t)d * DIM + lane * 4;
    asm volatile("red.global.add.v4.f32 [%0], {%1,%2,%3,%4};"
                 :: "l"(p), "f"(f.x), "f"(f.y), "f"(f.z), "f"(f.w)
                 : "memory");

    if (lane == 0) atomicAdd(g_deg + d, 1.0f);   // compiles to RED (no return use)
}

// ---------------------------------------------------------------------------
// Kernel 3: fused normalize + GEMM.  out[r] = (agg[r] * dinv[r]) @ W
// Block tile: 64 rows x 64 cols, 256 threads, 4x4 register blocking.
// ---------------------------------------------------------------------------
__global__ __launch_bounds__(256) void norm_gemm_kernel(
    const float* __restrict__ Wm,      // [64, 64] row-major (in, out)
    float*       __restrict__ out)     // [N, 64]
{
    __shared__ float Wsh[DIM][DIM];        // W[k][c]
    __shared__ float Hsh[DIM][DIM + 1];    // H[local_row][k], padded

    const int tid   = threadIdx.x;
    const int rbase = blockIdx.x * DIM;

    // Load W (4096 floats) cooperatively, vectorized.
    #pragma unroll
    for (int i = tid * 4; i < DIM * DIM; i += 256 * 4) {
        *(float4*)(&Wsh[0][0] + i) = __ldg((const float4*)(Wm + i));
    }

    // Load H tile: 4 threads per row, each thread 16 floats, scaled by dinv.
    {
        const int lr  = tid >> 2;        // local row 0..63
        const int seg = tid & 3;         // 16-float segment
        const int gr  = rbase + lr;
        if (gr < N_NODES) {
            float dinv = 1.0f / fmaxf(g_deg[gr], 1.0f);
            const float4* ap = (const float4*)(g_agg + (size_t)gr * DIM) + seg * 4;
            #pragma unroll
            for (int q = 0; q < 4; q++) {
                float4 v = ap[q];
                int k = seg * 16 + q * 4;
                Hsh[lr][k + 0] = v.x * dinv;
                Hsh[lr][k + 1] = v.y * dinv;
                Hsh[lr][k + 2] = v.z * dinv;
                Hsh[lr][k + 3] = v.w * dinv;
            }
        } else {
            #pragma unroll
            for (int q = 0; q < 16; q++) Hsh[lr][seg * 16 + q] = 0.f;
        }
    }
    __syncthreads();

    // Compute: thread (ty,tx) owns rows 4ty..4ty+3, cols 4tx..4tx+3.
    const int ty = tid >> 4;
    const int tx = tid & 15;
    float acc[4][4] = {};

    #pragma unroll 8
    for (int k = 0; k < DIM; k++) {
        float a0 = Hsh[4 * ty + 0][k];
        float a1 = Hsh[4 * ty + 1][k];
        float a2 = Hsh[4 * ty + 2][k];
        float a3 = Hsh[4 * ty + 3][k];
        float4 b = *(const float4*)&Wsh[k][4 * tx];
        acc[0][0] += a0 * b.x; acc[0][1] += a0 * b.y; acc[0][2] += a0 * b.z; acc[0][3] += a0 * b.w;
        acc[1][0] += a1 * b.x; acc[1][1] += a1 * b.y; acc[1][2] += a1 * b.z; acc[1][3] += a1 * b.w;
        acc[2][0] += a2 * b.x; acc[2][1] += a2 * b.y; acc[2][2] += a2 * b.z; acc[2][3] += a2 * b.w;
        acc[3][0] += a3 * b.x; acc[3][1] += a3 * b.y; acc[3][2] += a3 * b.z; acc[3][3] += a3 * b.w;
    }

    #pragma unroll
    for (int i = 0; i < 4; i++) {
        int r = rbase + 4 * ty + i;
        if (r < N_NODES) {
            *(float4*)(out + (size_t)r * DIM + 4 * tx) =
                make_float4(acc[i][0], acc[i][1], acc[i][2], acc[i][3]);
        }
    }
}

// ---------------------------------------------------------------------------
// kernel_launch: zero -> edge scatter -> fused normalize+GEMM (same stream)
// Inputs (metadata order): features, w, W, src, dst.  Output: float [N, 64].
// ---------------------------------------------------------------------------
extern "C" void kernel_launch(void* const* d_in, const int* in_sizes, int n_in,
                              void* d_out, int out_size)
{
    const float* feat = (const float*)d_in[0];
    const float* w    = (const float*)d_in[1];
    const float* Wm   = (const float*)d_in[2];
    const int*   src  = (const int*)d_in[3];
    const int*   dst  = (const int*)d_in[4];
    float*       out  = (float*)d_out;

    // zero: 1.6M float4 slots -> 6250 blocks covers both agg and deg
    {
        const size_t n4 = (size_t)N_NODES * DIM / 4;
        int grid = (int)((n4 + 255) / 256);
        zero_kernel<<<grid, 256>>>();
    }
    // edges: 16 threads per edge
    {
        long long threads = (long long)N_EDGES * 16;
        int grid = (int)((threads + 255) / 256);
        edge_kernel<<<grid, 256>>>(feat, w, src, dst);
    }
    // gemm: 64-row tiles
    {
        int grid = (N_NODES + DIM - 1) / DIM;
        norm_gemm_kernel<<<grid, 256>>>(Wm, out);
    }
}